// round 15
// baseline (speedup 1.0000x reference)
#include <cuda_runtime.h>
#include <math.h>

// Lloyd-Max LUT restricted to the nonnegative half: x_unit = (x - min)/scale >= 0,
// so searchsorted over all 15 boundaries reduces to 7 + #{j in 7..14 : b_j < xu}.
// Centroids/boundaries bit-match the reference via the FMA-free host Lloyd-Max
// below. b7f ~ +4e-5 > 0: xu==0 (the group-min element) -> centroid 7.
//
// Pipe balance: boundaries 7..10 -> FSETP/FSEL chain (ALU); boundaries 11..14 ->
// exact saturating-FMA steps (FMA): with BIG = 2^100 (power of two), b*BIG is
// exact, so sat(fma(xu, BIG, -b*BIG)) == (xu > b) ? 1 : 0 exactly, and the
// monotone staircase telescopes exactly via r += s_j * (c_{j+1} - c_j).
struct QLut {
    float c[5];      // centroids 7..11
    float b[4];      // boundaries 7..10 (compare part; b[0] ~ +4e-5)
    float nb[4];     // -b(11..14)*2^100 (exact)
    float d[4];      // c12-c11, c13-c12, c14-c13, c15-c14
};

#define BIG_F (0x1p100f)

__device__ __forceinline__ float sat_step(float xu, float negbBig) {
    float s;
    asm("fma.rn.sat.f32 %0, %1, %2, %3;" : "=f"(s) : "f"(xu), "f"(BIG_F), "f"(negbBig));
    return s;   // exactly 1.0f if xu > b, else 0.0f
}

__device__ __forceinline__ float quant_lookup(float xu, const QLut& lut) {
    float r = lut.c[0];
#pragma unroll
    for (int j = 0; j < 4; j++) {
        r = (xu > lut.b[j]) ? lut.c[j + 1] : r;           // ALU: FSETP + FSEL
    }
#pragma unroll
    for (int j = 0; j < 4; j++) {
        r = fmaf(sat_step(xu, lut.nb[j]), lut.d[j], r);   // FMA pipe
    }
    return r;
}

// 8 lanes per row, 16 elements per lane; 32 rows (one "chunk") per block-iter.
// Persistent grid-stride with software prefetch: the NEXT chunk's 4 LDG.128
// are issued before the current chunk's compute, so DRAM latency overlaps the
// ~350-cycle compute chain instead of serializing with it, and each warp keeps
// 4 loads in flight continuously. Block-uniform loop bounds (graph-safe).
__global__ void __launch_bounds__(256)
turboquant_kernel(const float4* __restrict__ in, float4* __restrict__ out,
                  unsigned nchunks, QLut lut) {
    unsigned tid    = threadIdx.x;
    unsigned lane8  = tid & 7u;
    unsigned rowOff = (tid >> 3) * 32u + lane8;           // float4 offset within chunk
    unsigned stride = gridDim.x;

    unsigned chunk = blockIdx.x;
    if (chunk >= nchunks) return;                         // block-uniform
    unsigned base = chunk * 1024u + rowOff;               // 32 rows * 32 float4 = 1024

    float4 v0 = __ldcs(in + base);
    float4 v1 = __ldcs(in + base + 8);
    float4 v2 = __ldcs(in + base + 16);
    float4 v3 = __ldcs(in + base + 24);

    for (;;) {
        // ---- prefetch next chunk (block-uniform predicate) ----
        unsigned nchunk = chunk + stride;
        bool more = (nchunk < nchunks);
        unsigned nbase = nchunk * 1024u + rowOff;
        float4 w0, w1, w2, w3;
        if (more) {
            w0 = __ldcs(in + nbase);
            w1 = __ldcs(in + nbase + 8);
            w2 = __ldcs(in + nbase + 16);
            w3 = __ldcs(in + nbase + 24);
        }

        // ---- thread-local min / sum / sum-of-squares over 16 elems ----
        float mn = fminf(fminf(fminf(fminf(v0.x, v0.y), fminf(v0.z, v0.w)),
                               fminf(fminf(v1.x, v1.y), fminf(v1.z, v1.w))),
                         fminf(fminf(fminf(v2.x, v2.y), fminf(v2.z, v2.w)),
                               fminf(fminf(v3.x, v3.y), fminf(v3.z, v3.w))));
        float sx = (((v0.x + v0.y) + (v0.z + v0.w)) + ((v1.x + v1.y) + (v1.z + v1.w)))
                 + (((v2.x + v2.y) + (v2.z + v2.w)) + ((v3.x + v3.y) + (v3.z + v3.w)));
        float sxx =
            fmaf(v0.x, v0.x, fmaf(v0.y, v0.y, fmaf(v0.z, v0.z, fmaf(v0.w, v0.w,
            fmaf(v1.x, v1.x, fmaf(v1.y, v1.y, fmaf(v1.z, v1.z, fmaf(v1.w, v1.w,
            fmaf(v2.x, v2.x, fmaf(v2.y, v2.y, fmaf(v2.z, v2.z, fmaf(v2.w, v2.w,
            fmaf(v3.x, v3.x, fmaf(v3.y, v3.y, fmaf(v3.z, v3.z, v3.w * v3.w)))))))))))))));

        // ---- one fused 3-stage butterfly for (min, sx, sxx) over 8 lanes ----
#pragma unroll
        for (int s = 4; s > 0; s >>= 1) {
            mn  = fminf(mn, __shfl_xor_sync(0xffffffffu, mn, s));
            sx  += __shfl_xor_sync(0xffffffffu, sx, s);
            sxx += __shfl_xor_sync(0xffffffffu, sxx, s);
        }

        // ss = sum((x-mn)^2) = sxx - 2*mn*sx + 128*mn^2 (closed form; no cancellation)
        float ss  = fmaf(mn, fmaf(128.0f, mn, -2.0f * sx), sxx);
        float vs  = __fsqrt_rn(ss) * 0.08838834764831845f;    // /sqrt(128)
        float inv = __fdividef(1.0f, vs + 1e-10f);

        // ---- centered + LUT quantize + gamma accumulation ----
        float r[16];
        float num = 0.0f, den = 0.0f;
        {
            const float4* vv[4] = {&v0, &v1, &v2, &v3};
#pragma unroll
            for (int q = 0; q < 4; q++) {
                float e0 = vv[q]->x - mn, e1 = vv[q]->y - mn;
                float e2 = vv[q]->z - mn, e3 = vv[q]->w - mn;
                float q0 = quant_lookup(e0 * inv, lut);
                float q1 = quant_lookup(e1 * inv, lut);
                float q2 = quant_lookup(e2 * inv, lut);
                float q3 = quant_lookup(e3 * inv, lut);
                num = fmaf(e0, q0, fmaf(e1, q1, fmaf(e2, q2, fmaf(e3, q3, num))));
                den = fmaf(q0, q0, fmaf(q1, q1, fmaf(q2, q2, fmaf(q3, q3, den))));
                r[q * 4 + 0] = q0; r[q * 4 + 1] = q1;
                r[q * 4 + 2] = q2; r[q * 4 + 3] = q3;
            }
        }

#pragma unroll
        for (int s = 4; s > 0; s >>= 1) {
            num += __shfl_xor_sync(0xffffffffu, num, s);
            den += __shfl_xor_sync(0xffffffffu, den, s);
        }
        float g = __fdividef(num, den + 1e-10f);

#pragma unroll
        for (int q = 0; q < 4; q++) {
            float4 o;
            o.x = fmaf(r[q * 4 + 0], g, mn);
            o.y = fmaf(r[q * 4 + 1], g, mn);
            o.z = fmaf(r[q * 4 + 2], g, mn);
            o.w = fmaf(r[q * 4 + 3], g, mn);
            __stcs(out + base + q * 8, o);
        }

        if (!more) break;
        v0 = w0; v1 = w1; v2 = w2; v3 = w3;
        base = nbase;
        chunk = nchunk;
    }
}

// ---------------------------------------------------------------------------
// Host: bit-faithful replication of the reference's discrete Lloyd-Max.
// CRITICAL: the linspace expression j*delta + (-10.0) must NOT fuse into an
// FMA (volatile breaks contraction), or the grid midpoint becomes +4.79e-16
// instead of exactly 0.0, the heaviest pdf point lands in the wrong bin, and
// the inner centroids shift ~9e-5 flipping the middle boundary's sign
// (the R2-R5 0.082/0.018 failures). Same for pdf*x. Capture-time only.
// ---------------------------------------------------------------------------
static void lloyd_laplace_centroids(float cf[16]) {
    static double xs[200001];
    static double pdf[200001];
    const int NX = 200001;
    const double delta = 20.0 / 200000.0;
    for (int j = 0; j < NX; j++) {
        volatile double prod = (double)j * delta;   // round the product first
        xs[j] = prod + (-10.0);                     // then round the add (no FMA)
    }
    xs[NX - 1] = 10.0;                              // numpy linspace endpoint
    for (int j = 0; j < NX; j++) pdf[j] = 0.5 * exp(-fabs(xs[j]));

    double c[16];
    for (int i = 0; i < 16; i++) {
        double p = ((double)i + 0.5) / 16.0;
        c[i] = (p < 0.5) ? log(2.0 * p) : -log(2.0 * (1.0 - p));
    }

    for (int it = 0; it < 200; it++) {
        double b[15];
        for (int i = 0; i < 15; i++) b[i] = 0.5 * (c[i + 1] + c[i]);
        double w[16], xw[16];
        for (int i = 0; i < 16; i++) { w[i] = 0.0; xw[i] = 0.0; }
        int bin = 0;  // xs ascending, boundaries ascending -> monotone advance
        for (int j = 0; j < NX; j++) {
            double x = xs[j];
            while (bin < 15 && b[bin] < x) bin++;   // searchsorted 'left'
            w[bin] += pdf[j];
            volatile double px = pdf[j] * x;        // round product (no FMA fuse)
            xw[bin] += px;
        }
        for (int i = 0; i < 16; i++) {
            if (w[i] > 0.0) c[i] = xw[i] / (w[i] > 1e-30 ? w[i] : 1e-30);
        }
    }
    for (int i = 0; i < 16; i++) cf[i] = (float)c[i];
}

extern "C" void kernel_launch(void* const* d_in, const int* in_sizes, int n_in,
                              void* d_out, int out_size) {
    (void)n_in; (void)out_size;
    const float4* in  = (const float4*)d_in[0];
    float4*       out = (float4*)d_out;

    int n       = in_sizes[0];
    int nrows   = n / 128;
    unsigned nchunks = (unsigned)((nrows + 31) / 32);    // 32 rows per chunk

    // Deterministic recompute every call (no caching per harness rules).
    float cf[16];
    lloyd_laplace_centroids(cf);
    // Boundaries in f32 exactly as the reference: 0.5f * (c[i+1] + c[i])
    float bf[15];
    for (int i = 0; i < 15; i++) bf[i] = 0.5f * (cf[i + 1] + cf[i]);

    QLut lut;
    for (int k = 0; k < 5; k++) lut.c[k] = cf[7 + k];        // centroids 7..11
    for (int k = 0; k < 4; k++) lut.b[k] = bf[7 + k];        // boundaries 7..10
    for (int k = 0; k < 4; k++) {
        lut.nb[k] = -(bf[11 + k] * BIG_F);                   // exact: BIG is 2^100
        lut.d[k]  = cf[12 + k] - cf[11 + k];
    }

    // Persistent-ish grid: long-lived blocks, ~8 chunks each at full size.
    unsigned grid = nchunks < 2048u ? nchunks : 2048u;
    turboquant_kernel<<<grid, 256>>>(in, out, nchunks, lut);
}

// round 17
// speedup vs baseline: 1.0260x; 1.0260x over previous
#include <cuda_runtime.h>
#include <math.h>

// Lloyd-Max LUT restricted to the nonnegative half: x_unit = (x - min)/scale >= 0,
// so searchsorted over all 15 boundaries reduces to 7 + #{j in 7..14 : b_j < xu}.
// Centroids/boundaries bit-match the reference via the FMA-free host Lloyd-Max
// below. b7f ~ +4e-5 > 0: xu==0 (the group-min element) -> centroid 7.
//
// Pipe balance (3/5 split; ALU and FMA pipes have equal throughput):
//   boundaries 7..9   -> FSETP/FSEL chain (ALU pipe), centroids 7..10
//   boundaries 10..14 -> exact saturating-FMA steps (FMA pipe):
//     with BIG = 2^100 (power of two), b*BIG is exact, so
//     sat(fma(xu, BIG, -b*BIG)) == (xu > b) ? 1.0f : 0.0f exactly, and
//     r += s_j * (c_{j+1} - c_j) telescopes the monotone staircase exactly.
struct QLut {
    float c[4];      // centroids 7..10
    float b[3];      // boundaries 7..9 (compare part; b[0] ~ +4e-5)
    float nb[5];     // -b(10..14)*2^100 (exact)
    float d[5];      // c11-c10 ... c15-c14
};

#define BIG_F (0x1p100f)

__device__ __forceinline__ float sat_step(float xu, float negbBig) {
    float s;
    asm("fma.rn.sat.f32 %0, %1, %2, %3;" : "=f"(s) : "f"(xu), "f"(BIG_F), "f"(negbBig));
    return s;   // exactly 1.0f if xu > b, else 0.0f
}

__device__ __forceinline__ float quant_lookup(float xu, const QLut& lut) {
    float r = lut.c[0];
#pragma unroll
    for (int j = 0; j < 3; j++) {
        r = (xu > lut.b[j]) ? lut.c[j + 1] : r;           // ALU: FSETP + FSEL
    }
#pragma unroll
    for (int j = 0; j < 5; j++) {
        r = fmaf(sat_step(xu, lut.nb[j]), lut.d[j], r);   // FMA pipe
    }
    return r;
}

// 8 lanes per row, 16 elements per lane. shfl_xor with s in {4,2,1} stays
// within each 8-lane group, so four rows reduce independently in one warp.
// Stream-once data: __ldcs/__stcs evict-first hints. 32-bit addressing.
// (R14 shape — best measured config; persistent/prefetch variants regressed.)
__global__ void __launch_bounds__(256)
turboquant_kernel(const float4* __restrict__ in, float4* __restrict__ out,
                  int nrows, QLut lut) {
    unsigned tid   = threadIdx.x;
    unsigned lane8 = tid & 7u;
    unsigned row   = (blockIdx.x << 5) + (tid >> 3);      // 32 rows per block
    if (row >= (unsigned)nrows) return;                   // warp-uniform (never taken)
    unsigned base = row * 32u + lane8;                    // float4 units; row = 32 float4

    float4 v0 = __ldcs(in + base);                        // 4 independent 128B loads
    float4 v1 = __ldcs(in + base + 8);
    float4 v2 = __ldcs(in + base + 16);
    float4 v3 = __ldcs(in + base + 24);

    // ---- thread-local min / sum / sum-of-squares over 16 elems ----
    float mn = fminf(fminf(fminf(fminf(v0.x, v0.y), fminf(v0.z, v0.w)),
                           fminf(fminf(v1.x, v1.y), fminf(v1.z, v1.w))),
                     fminf(fminf(fminf(v2.x, v2.y), fminf(v2.z, v2.w)),
                           fminf(fminf(v3.x, v3.y), fminf(v3.z, v3.w))));
    float sx = (((v0.x + v0.y) + (v0.z + v0.w)) + ((v1.x + v1.y) + (v1.z + v1.w)))
             + (((v2.x + v2.y) + (v2.z + v2.w)) + ((v3.x + v3.y) + (v3.z + v3.w)));
    float sxx =
        fmaf(v0.x, v0.x, fmaf(v0.y, v0.y, fmaf(v0.z, v0.z, fmaf(v0.w, v0.w,
        fmaf(v1.x, v1.x, fmaf(v1.y, v1.y, fmaf(v1.z, v1.z, fmaf(v1.w, v1.w,
        fmaf(v2.x, v2.x, fmaf(v2.y, v2.y, fmaf(v2.z, v2.z, fmaf(v2.w, v2.w,
        fmaf(v3.x, v3.x, fmaf(v3.y, v3.y, fmaf(v3.z, v3.z, v3.w * v3.w)))))))))))))));

    // ---- one fused 3-stage butterfly for (min, sx, sxx) over 8 lanes ----
#pragma unroll
    for (int s = 4; s > 0; s >>= 1) {
        mn  = fminf(mn, __shfl_xor_sync(0xffffffffu, mn, s));
        sx  += __shfl_xor_sync(0xffffffffu, sx, s);
        sxx += __shfl_xor_sync(0xffffffffu, sxx, s);
    }

    // ss = sum((x-mn)^2) = sxx - 2*mn*sx + 128*mn^2 (closed form; no cancellation)
    float ss  = fmaf(mn, fmaf(128.0f, mn, -2.0f * sx), sxx);
    float vs  = __fsqrt_rn(ss) * 0.08838834764831845f;    // /sqrt(128)
    float inv = __fdividef(1.0f, vs + 1e-10f);

    // ---- centered + LUT quantize + gamma accumulation ----
    float r[16];
    float num = 0.0f, den = 0.0f;
    {
        const float4* vv[4] = {&v0, &v1, &v2, &v3};
#pragma unroll
        for (int q = 0; q < 4; q++) {
            float e0 = vv[q]->x - mn, e1 = vv[q]->y - mn;
            float e2 = vv[q]->z - mn, e3 = vv[q]->w - mn;
            float q0 = quant_lookup(e0 * inv, lut);
            float q1 = quant_lookup(e1 * inv, lut);
            float q2 = quant_lookup(e2 * inv, lut);
            float q3 = quant_lookup(e3 * inv, lut);
            num = fmaf(e0, q0, fmaf(e1, q1, fmaf(e2, q2, fmaf(e3, q3, num))));
            den = fmaf(q0, q0, fmaf(q1, q1, fmaf(q2, q2, fmaf(q3, q3, den))));
            r[q * 4 + 0] = q0; r[q * 4 + 1] = q1;
            r[q * 4 + 2] = q2; r[q * 4 + 3] = q3;
        }
    }

#pragma unroll
    for (int s = 4; s > 0; s >>= 1) {
        num += __shfl_xor_sync(0xffffffffu, num, s);
        den += __shfl_xor_sync(0xffffffffu, den, s);
    }
    float g = __fdividef(num, den + 1e-10f);

#pragma unroll
    for (int q = 0; q < 4; q++) {
        float4 o;
        o.x = fmaf(r[q * 4 + 0], g, mn);
        o.y = fmaf(r[q * 4 + 1], g, mn);
        o.z = fmaf(r[q * 4 + 2], g, mn);
        o.w = fmaf(r[q * 4 + 3], g, mn);
        __stcs(out + base + q * 8, o);
    }
}

// ---------------------------------------------------------------------------
// Host: bit-faithful replication of the reference's discrete Lloyd-Max.
// CRITICAL: the linspace expression j*delta + (-10.0) must NOT fuse into an
// FMA (volatile breaks contraction), or the grid midpoint becomes +4.79e-16
// instead of exactly 0.0, the heaviest pdf point lands in the wrong bin, and
// the inner centroids shift ~9e-5 flipping the middle boundary's sign
// (the R2-R5 0.082/0.018 failures). Same for pdf*x. Capture-time only.
// ---------------------------------------------------------------------------
static void lloyd_laplace_centroids(float cf[16]) {
    static double xs[200001];
    static double pdf[200001];
    const int NX = 200001;
    const double delta = 20.0 / 200000.0;
    for (int j = 0; j < NX; j++) {
        volatile double prod = (double)j * delta;   // round the product first
        xs[j] = prod + (-10.0);                     // then round the add (no FMA)
    }
    xs[NX - 1] = 10.0;                              // numpy linspace endpoint
    for (int j = 0; j < NX; j++) pdf[j] = 0.5 * exp(-fabs(xs[j]));

    double c[16];
    for (int i = 0; i < 16; i++) {
        double p = ((double)i + 0.5) / 16.0;
        c[i] = (p < 0.5) ? log(2.0 * p) : -log(2.0 * (1.0 - p));
    }

    for (int it = 0; it < 200; it++) {
        double b[15];
        for (int i = 0; i < 15; i++) b[i] = 0.5 * (c[i + 1] + c[i]);
        double w[16], xw[16];
        for (int i = 0; i < 16; i++) { w[i] = 0.0; xw[i] = 0.0; }
        int bin = 0;  // xs ascending, boundaries ascending -> monotone advance
        for (int j = 0; j < NX; j++) {
            double x = xs[j];
            while (bin < 15 && b[bin] < x) bin++;   // searchsorted 'left'
            w[bin] += pdf[j];
            volatile double px = pdf[j] * x;        // round product (no FMA fuse)
            xw[bin] += px;
        }
        for (int i = 0; i < 16; i++) {
            if (w[i] > 0.0) c[i] = xw[i] / (w[i] > 1e-30 ? w[i] : 1e-30);
        }
    }
    for (int i = 0; i < 16; i++) cf[i] = (float)c[i];
}

extern "C" void kernel_launch(void* const* d_in, const int* in_sizes, int n_in,
                              void* d_out, int out_size) {
    (void)n_in; (void)out_size;
    const float4* in  = (const float4*)d_in[0];
    float4*       out = (float4*)d_out;

    int n     = in_sizes[0];
    int nrows = n / 128;

    // Deterministic recompute every call (no caching per harness rules).
    float cf[16];
    lloyd_laplace_centroids(cf);
    // Boundaries in f32 exactly as the reference: 0.5f * (c[i+1] + c[i])
    float bf[15];
    for (int i = 0; i < 15; i++) bf[i] = 0.5f * (cf[i + 1] + cf[i]);

    QLut lut;
    for (int k = 0; k < 4; k++) lut.c[k] = cf[7 + k];        // centroids 7..10
    for (int k = 0; k < 3; k++) lut.b[k] = bf[7 + k];        // boundaries 7..9
    for (int k = 0; k < 5; k++) {
        lut.nb[k] = -(bf[10 + k] * BIG_F);                   // exact: BIG is 2^100
        lut.d[k]  = cf[11 + k] - cf[10 + k];
    }

    int blocks = (nrows + 31) / 32;                          // 32 rows per block
    turboquant_kernel<<<blocks, 256>>>(in, out, nrows, lut);
}